// round 1
// baseline (speedup 1.0000x reference)
#include <cuda_runtime.h>
#include <cuda_bf16.h>
#include <math.h>

#define D 4096
#define H 2
#define HD (D / H)     // 2048
#define E 8192

// Scratch (device globals — no allocations allowed). Fully overwritten every run.
__device__ float g_x[2 * D];        // embeddings / attention input
__device__ float g_qkv[2 * 3 * D];  // packed qkv
__device__ float g_o[2 * D];        // attention output (pre out-proj)
__device__ float g_x1[2 * D];       // after residual 1
__device__ float g_h[2 * D];        // ffn hidden
__device__ float g_x2[2 * D];       // after residual 2
__device__ float g_g[2 * E];        // expert hidden

// ---------------------------------------------------------------------------
// Stage 0: per-task embeddings  x[l][i] = relu(ray[l]*emb_w[i] + emb_b[i])
// ---------------------------------------------------------------------------
__global__ void k_embed(const float* __restrict__ ray,
                        const float* __restrict__ w1, const float* __restrict__ b1,
                        const float* __restrict__ w2, const float* __restrict__ b2) {
    int i = blockIdx.x * blockDim.x + threadIdx.x;
    if (i < D) {
        float r0 = __ldg(ray + 0);
        float r1 = __ldg(ray + 1);
        g_x[i]     = fmaxf(r0 * w1[i] + b1[i], 0.0f);
        g_x[D + i] = fmaxf(r1 * w2[i] + b2[i], 0.0f);
    }
}

// ---------------------------------------------------------------------------
// Generic 2-row GEMV: out[l][j] = f( dot(xin[l], W[j,:]) + b[j] (+ resid[l][j]) )
// One warp per output row j; weight row (16 KB) streamed via float4.
// Both sequence positions computed per weight load (weights read once).
// ---------------------------------------------------------------------------
template <bool RELU, bool RESID>
__global__ void k_gemv2(const float* __restrict__ W,
                        const float* __restrict__ b,
                        const float* __restrict__ xin,     // [2][K]
                        const float* __restrict__ resid,   // [2][N] or null
                        float* __restrict__ out,           // [2][N]
                        int N, int K) {
    const int warp = threadIdx.x >> 5;
    const int lane = threadIdx.x & 31;
    const int j = blockIdx.x * (blockDim.x >> 5) + warp;
    if (j >= N) return;

    const float4* __restrict__ w4 = reinterpret_cast<const float4*>(W + (size_t)j * K);
    const float4* __restrict__ x0 = reinterpret_cast<const float4*>(xin);
    const float4* __restrict__ x1 = reinterpret_cast<const float4*>(xin + K);

    float a0 = 0.0f, a1 = 0.0f;
    const int K4 = K >> 2;
#pragma unroll 4
    for (int i = lane; i < K4; i += 32) {
        float4 w = w4[i];
        float4 p = x0[i];
        float4 q = x1[i];
        a0 += w.x * p.x + w.y * p.y + w.z * p.z + w.w * p.w;
        a1 += w.x * q.x + w.y * q.y + w.z * q.z + w.w * q.w;
    }
#pragma unroll
    for (int off = 16; off; off >>= 1) {
        a0 += __shfl_xor_sync(0xFFFFFFFFu, a0, off);
        a1 += __shfl_xor_sync(0xFFFFFFFFu, a1, off);
    }
    if (lane == 0) {
        float bb = b ? b[j] : 0.0f;
        float r0 = a0 + bb;
        float r1 = a1 + bb;
        if (RESID) { r0 += resid[j]; r1 += resid[N + j]; }
        if (RELU)  { r0 = fmaxf(r0, 0.0f); r1 = fmaxf(r1, 0.0f); }
        out[j]     = r0;
        out[N + j] = r1;
    }
}

// ---------------------------------------------------------------------------
// Stage 2: multi-head attention on the 2-token sequence (tiny; one block).
// scores[h][l][m] = dot(q[l,h], k[m,h]) / sqrt(HD);  softmax over m;
// o[l][h*HD+d] = sum_m attn[h][l][m] * v[m][h*HD+d]
// ---------------------------------------------------------------------------
__global__ void k_attn() {
    __shared__ float s_scores[8];  // index: h*4 + l*2 + m
    __shared__ float s_attn[8];
    const int tid = threadIdx.x;          // 256 threads = 8 warps
    const int warp = tid >> 5, lane = tid & 31;

    // one warp per (h, l, m) combination
    const int h = warp >> 2, l = (warp >> 1) & 1, m = warp & 1;
    const float* __restrict__ q = g_qkv + l * 3 * D + h * HD;
    const float* __restrict__ k = g_qkv + m * 3 * D + D + h * HD;
    float acc = 0.0f;
#pragma unroll 4
    for (int i = lane; i < HD; i += 32) acc += q[i] * k[i];
#pragma unroll
    for (int off = 16; off; off >>= 1) acc += __shfl_xor_sync(0xFFFFFFFFu, acc, off);
    if (lane == 0) s_scores[warp] = acc * rsqrtf((float)HD);
    __syncthreads();

    if (tid < 4) {  // (h, l) pairs: softmax over m (2 elements)
        int hh = tid >> 1, ll = tid & 1;
        float s0 = s_scores[hh * 4 + ll * 2 + 0];
        float s1 = s_scores[hh * 4 + ll * 2 + 1];
        float mx = fmaxf(s0, s1);
        float e0 = __expf(s0 - mx), e1 = __expf(s1 - mx);
        float inv = 1.0f / (e0 + e1);
        s_attn[hh * 4 + ll * 2 + 0] = e0 * inv;
        s_attn[hh * 4 + ll * 2 + 1] = e1 * inv;
    }
    __syncthreads();

    for (int i = tid; i < 2 * D; i += blockDim.x) {
        int l2 = i / D;
        int d = i - l2 * D;
        int h2 = d / HD;
        float v0 = g_qkv[0 * 3 * D + 2 * D + d];
        float v1 = g_qkv[1 * 3 * D + 2 * D + d];
        g_o[i] = s_attn[h2 * 4 + l2 * 2 + 0] * v0 +
                 s_attn[h2 * 4 + l2 * 2 + 1] * v1;
    }
}

// ---------------------------------------------------------------------------
// Stage 7: out = mean_l( dot(g[l], exp_w2) + exp_b2 )
//        = 0.5 * dot(g0 + g1, exp_w2) + exp_b2
// ---------------------------------------------------------------------------
__global__ void k_final(const float* __restrict__ w2,
                        const float* __restrict__ b2,
                        float* __restrict__ out) {
    __shared__ float red[8];
    float acc = 0.0f;
    for (int i = threadIdx.x; i < E; i += blockDim.x)
        acc += (g_g[i] + g_g[E + i]) * w2[i];
#pragma unroll
    for (int off = 16; off; off >>= 1) acc += __shfl_xor_sync(0xFFFFFFFFu, acc, off);
    const int warp = threadIdx.x >> 5, lane = threadIdx.x & 31;
    if (lane == 0) red[warp] = acc;
    __syncthreads();
    if (threadIdx.x == 0) {
        float s = 0.0f;
        for (int w = 0; w < 8; ++w) s += red[w];
        out[0] = 0.5f * s + b2[0];
    }
}

// ---------------------------------------------------------------------------
extern "C" void kernel_launch(void* const* d_in, const int* in_sizes, int n_in,
                              void* d_out, int out_size) {
    const float* ray        = (const float*)d_in[0];
    const float* emb1_w     = (const float*)d_in[1];
    const float* emb1_b     = (const float*)d_in[2];
    const float* emb2_w     = (const float*)d_in[3];
    const float* emb2_b     = (const float*)d_in[4];
    const float* attn_in_w  = (const float*)d_in[5];
    const float* attn_in_b  = (const float*)d_in[6];
    const float* attn_out_w = (const float*)d_in[7];
    const float* attn_out_b = (const float*)d_in[8];
    const float* ffn1_w     = (const float*)d_in[9];
    const float* ffn1_b     = (const float*)d_in[10];
    const float* ffn2_w     = (const float*)d_in[11];
    const float* ffn2_b     = (const float*)d_in[12];
    const float* exp_w1     = (const float*)d_in[13];
    const float* exp_b1     = (const float*)d_in[14];
    const float* exp_w2     = (const float*)d_in[15];
    const float* exp_b2     = (const float*)d_in[16];
    // d_in[17] = idx (always 0, single expert) — unused
    float* out = (float*)d_out;

    float *px, *pqkv, *po, *px1, *ph, *px2, *pg;
    cudaGetSymbolAddress((void**)&px,   g_x);
    cudaGetSymbolAddress((void**)&pqkv, g_qkv);
    cudaGetSymbolAddress((void**)&po,   g_o);
    cudaGetSymbolAddress((void**)&px1,  g_x1);
    cudaGetSymbolAddress((void**)&ph,   g_h);
    cudaGetSymbolAddress((void**)&px2,  g_x2);
    cudaGetSymbolAddress((void**)&pg,   g_g);

    const int WPB = 8;   // warps (output rows) per block
    dim3 blk(256);

    // 0: embeddings -> g_x [2][D]
    k_embed<<<(D + 255) / 256, 256>>>(ray, emb1_w, emb1_b, emb2_w, emb2_b);

    // 1: qkv = x @ attn_in_w^T + b  -> g_qkv [2][3D]   (201 MB of weights)
    k_gemv2<false, false><<<(3 * D) / WPB, blk>>>(attn_in_w, attn_in_b, px, nullptr, pqkv, 3 * D, D);

    // 2: attention -> g_o [2][D]
    k_attn<<<1, 256>>>();

    // 3: x1 = x + o @ attn_out_w^T + b
    k_gemv2<false, true><<<D / WPB, blk>>>(attn_out_w, attn_out_b, po, px, px1, D, D);

    // 4: h = relu(x1 @ ffn1_w^T + b1)
    k_gemv2<true, false><<<D / WPB, blk>>>(ffn1_w, ffn1_b, px1, nullptr, ph, D, D);

    // 5: x2 = x1 + h @ ffn2_w^T + b2
    k_gemv2<false, true><<<D / WPB, blk>>>(ffn2_w, ffn2_b, ph, px1, px2, D, D);

    // 6: g = relu(x2 @ exp_w1^T + b1)  -> [2][E]   (134 MB of weights)
    k_gemv2<true, false><<<E / WPB, blk>>>(exp_w1, exp_b1, px2, nullptr, pg, E, D);

    // 7: out = mean over seq of (g @ exp_w2^T + b2)
    k_final<<<1, 256>>>(exp_w2, exp_b2, out);
}

// round 3
// speedup vs baseline: 1.1532x; 1.1532x over previous
#include <cuda_runtime.h>
#include <cuda_bf16.h>
#include <math.h>

#define D 4096
#define H 2
#define HD (D / H)     // 2048
#define E 8192

// Scratch (device globals — no allocations allowed). Fully overwritten every run.
__device__ float g_x[2 * D];        // embeddings / attention input
__device__ float g_qkv[2 * 3 * D];  // packed qkv
__device__ float g_o[2 * D];        // attention output (pre out-proj)
__device__ float g_x1[2 * D];       // after residual 1
__device__ float g_h[2 * D];        // ffn hidden
__device__ float g_x2[2 * D];       // after residual 2
__device__ float g_g[2 * E];        // expert hidden

// ---------------------------------------------------------------------------
// Stage 0: per-task embeddings  x[l][i] = relu(ray[l]*emb_w[i] + emb_b[i])
// ---------------------------------------------------------------------------
__global__ void k_embed(const float* __restrict__ ray,
                        const float* __restrict__ w1, const float* __restrict__ b1,
                        const float* __restrict__ w2, const float* __restrict__ b2) {
    int i = blockIdx.x * blockDim.x + threadIdx.x;
    if (i < D) {
        float r0 = __ldg(ray + 0);
        float r1 = __ldg(ray + 1);
        g_x[i]     = fmaxf(r0 * w1[i] + b1[i], 0.0f);
        g_x[D + i] = fmaxf(r1 * w2[i] + b2[i], 0.0f);
    }
}

// ---------------------------------------------------------------------------
// 2-row GEMV, one 256-thread block per output row, compile-time K.
// All weight loads for the row are issued before any FMA (front-batched MLP).
// x vectors (32 KB) are L1-resident after the first block on each SM.
// ---------------------------------------------------------------------------
template <int KK, bool RELU, bool RESID>
__global__ void __launch_bounds__(256)
k_gemv_row(const float* __restrict__ W,
           const float* __restrict__ b,
           const float* __restrict__ xin,     // [2][KK]
           const float* __restrict__ resid,   // [2][N] or null
           float* __restrict__ out,           // [2][N]
           int N) {
    constexpr int K4 = KK / 4;          // float4 elements per row
    constexpr int IT = K4 / 256;        // iterations per thread (4 for K=4096)

    const int j = blockIdx.x;
    const int tid = threadIdx.x;

    const float4* __restrict__ w4 = reinterpret_cast<const float4*>(W + (size_t)j * KK);
    const float4* __restrict__ x0 = reinterpret_cast<const float4*>(xin);
    const float4* __restrict__ x1 = reinterpret_cast<const float4*>(xin + KK);

    // Front-batch all weight loads (independent LDG.128s -> deep MLP).
    float4 w[IT];
#pragma unroll
    for (int t = 0; t < IT; ++t) w[t] = w4[t * 256 + tid];

    float a0 = 0.0f, a1 = 0.0f;
#pragma unroll
    for (int t = 0; t < IT; ++t) {
        float4 p = x0[t * 256 + tid];
        float4 q = x1[t * 256 + tid];
        a0 += w[t].x * p.x + w[t].y * p.y + w[t].z * p.z + w[t].w * p.w;
        a1 += w[t].x * q.x + w[t].y * q.y + w[t].z * q.z + w[t].w * q.w;
    }

    // Block reduction: warp shuffle then smem across 8 warps.
#pragma unroll
    for (int off = 16; off; off >>= 1) {
        a0 += __shfl_xor_sync(0xFFFFFFFFu, a0, off);
        a1 += __shfl_xor_sync(0xFFFFFFFFu, a1, off);
    }
    __shared__ float s0[8], s1[8];
    const int warp = tid >> 5, lane = tid & 31;
    if (lane == 0) { s0[warp] = a0; s1[warp] = a1; }
    __syncthreads();
    if (tid == 0) {
        float r0 = 0.0f, r1 = 0.0f;
#pragma unroll
        for (int wI = 0; wI < 8; ++wI) { r0 += s0[wI]; r1 += s1[wI]; }
        float bb = b ? b[j] : 0.0f;
        r0 += bb; r1 += bb;
        if (RESID) { r0 += resid[j]; r1 += resid[N + j]; }
        if (RELU)  { r0 = fmaxf(r0, 0.0f); r1 = fmaxf(r1, 0.0f); }
        out[j]     = r0;
        out[N + j] = r1;
    }
}

// ---------------------------------------------------------------------------
// Stage 2: multi-head attention on the 2-token sequence (tiny; one block).
// ---------------------------------------------------------------------------
__global__ void k_attn() {
    __shared__ float s_scores[8];  // index: h*4 + l*2 + m
    __shared__ float s_attn[8];
    const int tid = threadIdx.x;          // 256 threads = 8 warps
    const int warp = tid >> 5, lane = tid & 31;

    // one warp per (h, l, m) combination
    const int h = warp >> 2, l = (warp >> 1) & 1, m = warp & 1;
    const float* __restrict__ q = g_qkv + l * 3 * D + h * HD;
    const float* __restrict__ k = g_qkv + m * 3 * D + D + h * HD;
    float acc = 0.0f;
#pragma unroll 4
    for (int i = lane; i < HD; i += 32) acc += q[i] * k[i];
#pragma unroll
    for (int off = 16; off; off >>= 1) acc += __shfl_xor_sync(0xFFFFFFFFu, acc, off);
    if (lane == 0) s_scores[warp] = acc * rsqrtf((float)HD);
    __syncthreads();

    if (tid < 4) {  // (h, l) pairs: softmax over m (2 elements)
        int hh = tid >> 1, ll = tid & 1;
        float s0v = s_scores[hh * 4 + ll * 2 + 0];
        float s1v = s_scores[hh * 4 + ll * 2 + 1];
        float mx = fmaxf(s0v, s1v);
        float e0 = __expf(s0v - mx), e1 = __expf(s1v - mx);
        float inv = 1.0f / (e0 + e1);
        s_attn[hh * 4 + ll * 2 + 0] = e0 * inv;
        s_attn[hh * 4 + ll * 2 + 1] = e1 * inv;
    }
    __syncthreads();

    for (int i = tid; i < 2 * D; i += blockDim.x) {
        int l2 = i / D;
        int d = i - l2 * D;
        int h2 = d / HD;
        float v0 = g_qkv[0 * 3 * D + 2 * D + d];
        float v1 = g_qkv[1 * 3 * D + 2 * D + d];
        g_o[i] = s_attn[h2 * 4 + l2 * 2 + 0] * v0 +
                 s_attn[h2 * 4 + l2 * 2 + 1] * v1;
    }
}

// ---------------------------------------------------------------------------
// Stage 7: out = 0.5 * dot(g0 + g1, exp_w2) + exp_b2
// ---------------------------------------------------------------------------
__global__ void k_final(const float* __restrict__ w2,
                        const float* __restrict__ b2,
                        float* __restrict__ out) {
    __shared__ float red[32];
    float acc = 0.0f;
    for (int i = threadIdx.x; i < E; i += blockDim.x)
        acc += (g_g[i] + g_g[E + i]) * w2[i];
#pragma unroll
    for (int off = 16; off; off >>= 1) acc += __shfl_xor_sync(0xFFFFFFFFu, acc, off);
    const int warp = threadIdx.x >> 5, lane = threadIdx.x & 31;
    if (lane == 0) red[warp] = acc;
    __syncthreads();
    if (threadIdx.x == 0) {
        float s = 0.0f;
        const int nw = blockDim.x >> 5;
        for (int w = 0; w < nw; ++w) s += red[w];
        out[0] = 0.5f * s + b2[0];
    }
}

// ---------------------------------------------------------------------------
extern "C" void kernel_launch(void* const* d_in, const int* in_sizes, int n_in,
                              void* d_out, int out_size) {
    const float* ray        = (const float*)d_in[0];
    const float* emb1_w     = (const float*)d_in[1];
    const float* emb1_b     = (const float*)d_in[2];
    const float* emb2_w     = (const float*)d_in[3];
    const float* emb2_b     = (const float*)d_in[4];
    const float* attn_in_w  = (const float*)d_in[5];
    const float* attn_in_b  = (const float*)d_in[6];
    const float* attn_out_w = (const float*)d_in[7];
    const float* attn_out_b = (const float*)d_in[8];
    const float* ffn1_w     = (const float*)d_in[9];
    const float* ffn1_b     = (const float*)d_in[10];
    const float* ffn2_w     = (const float*)d_in[11];
    const float* ffn2_b     = (const float*)d_in[12];
    const float* exp_w1     = (const float*)d_in[13];
    const float* exp_b1     = (const float*)d_in[14];
    const float* exp_w2     = (const float*)d_in[15];
    const float* exp_b2     = (const float*)d_in[16];
    // d_in[17] = idx (always 0, single expert) — unused
    float* out = (float*)d_out;

    float *px, *pqkv, *po, *px1, *ph, *px2;
    cudaGetSymbolAddress((void**)&px,   g_x);
    cudaGetSymbolAddress((void**)&pqkv, g_qkv);
    cudaGetSymbolAddress((void**)&po,   g_o);
    cudaGetSymbolAddress((void**)&px1,  g_x1);
    cudaGetSymbolAddress((void**)&ph,   g_h);
    cudaGetSymbolAddress((void**)&px2,  g_x2);
    float* pg;
    cudaGetSymbolAddress((void**)&pg,   g_g);

    // 0: embeddings -> g_x [2][D]
    k_embed<<<(D + 255) / 256, 256>>>(ray, emb1_w, emb1_b, emb2_w, emb2_b);

    // 1: qkv = x @ attn_in_w^T + b  -> g_qkv [2][3D]   (201 MB of weights)
    k_gemv_row<D, false, false><<<3 * D, 256>>>(attn_in_w, attn_in_b, px, nullptr, pqkv, 3 * D);

    // 2: attention -> g_o [2][D]
    k_attn<<<1, 256>>>();

    // 3: x1 = x + o @ attn_out_w^T + b
    k_gemv_row<D, false, true><<<D, 256>>>(attn_out_w, attn_out_b, po, px, px1, D);

    // 4: h = relu(x1 @ ffn1_w^T + b1)
    k_gemv_row<D, true, false><<<D, 256>>>(ffn1_w, ffn1_b, px1, nullptr, ph, D);

    // 5: x2 = x1 + h @ ffn2_w^T + b2
    k_gemv_row<D, false, true><<<D, 256>>>(ffn2_w, ffn2_b, ph, px1, px2, D);

    // 6: g = relu(x2 @ exp_w1^T + b1)  -> [2][E]   (134 MB of weights)
    k_gemv_row<D, true, false><<<E, 256>>>(exp_w1, exp_b1, px2, nullptr, pg, E);

    // 7: out = mean over seq of (g @ exp_w2^T + b2)
    k_final<<<1, 1024>>>(exp_w2, exp_b2, out);
}

// round 5
// speedup vs baseline: 1.2938x; 1.1220x over previous
#include <cuda_runtime.h>
#include <cuda_bf16.h>
#include <math.h>

#define D 4096
#define H 2
#define HD (D / H)     // 2048
#define E 8192

// Scratch (device globals — no allocations allowed). Fully overwritten every run.
__device__ float g_x[2 * D];        // embeddings / attention input
__device__ float g_qkv[2 * 3 * D];  // packed qkv
__device__ float g_o[2 * D];        // attention output (pre out-proj)
__device__ float g_x1[2 * D];       // after residual 1
__device__ float g_h[2 * D];        // ffn hidden
__device__ float g_x2[2 * D];       // after residual 2
__device__ float g_g[2 * E];        // expert hidden

// ---------------------------------------------------------------------------
// Stage 0: per-task embeddings  x[l][i] = relu(ray[l]*emb_w[i] + emb_b[i])
// ---------------------------------------------------------------------------
__global__ void k_embed(const float* __restrict__ ray,
                        const float* __restrict__ w1, const float* __restrict__ b1,
                        const float* __restrict__ w2, const float* __restrict__ b2) {
    int i = blockIdx.x * blockDim.x + threadIdx.x;
    if (i < D) {
        float r0 = __ldg(ray + 0);
        float r1 = __ldg(ray + 1);
        g_x[i]     = fmaxf(r0 * w1[i] + b1[i], 0.0f);
        g_x[D + i] = fmaxf(r1 * w2[i] + b2[i], 0.0f);
    }
}

// ---------------------------------------------------------------------------
// Pipelined 2-row GEMV: one 256-thread block handles RPB consecutive output
// rows. Weight loads for row r+1 are issued (double-buffered in registers)
// before the FMAs of row r, so LDG issue is continuous — no dead time during
// reduction. x-vectors are loaded to registers ONCE per block and reused for
// all RPB rows. Cross-warp reduction of all rows deferred to one barrier.
// ---------------------------------------------------------------------------
template <int KK, bool RELU, bool RESID, int RPB>
__global__ void __launch_bounds__(256)
k_gemv_pipe(const float* __restrict__ W,
            const float* __restrict__ b,
            const float* __restrict__ xin,     // [2][KK]
            const float* __restrict__ resid,   // [2][N] or null
            float* __restrict__ out,           // [2][N]
            int N) {
    constexpr int K4 = KK / 4;          // float4 per row (1024 for K=4096)
    constexpr int IT = K4 / 256;        // float4 per thread per row (4)

    const int tid  = threadIdx.x;
    const int warp = tid >> 5, lane = tid & 31;
    const int row0 = blockIdx.x * RPB;

    __shared__ float s0[RPB][8];
    __shared__ float s1[RPB][8];

    // x vectors cached in registers for the whole block lifetime.
    const float4* __restrict__ x0 = reinterpret_cast<const float4*>(xin);
    const float4* __restrict__ x1 = reinterpret_cast<const float4*>(xin + KK);
    float4 xa[IT], xb[IT];
#pragma unroll
    for (int t = 0; t < IT; ++t) { xa[t] = x0[t * 256 + tid]; xb[t] = x1[t * 256 + tid]; }

    // Prologue: load row0 weights.
    float4 wc[IT];
    {
        const float4* __restrict__ wr = reinterpret_cast<const float4*>(W + (size_t)row0 * KK);
#pragma unroll
        for (int t = 0; t < IT; ++t) wc[t] = wr[t * 256 + tid];
    }

#pragma unroll
    for (int r = 0; r < RPB; ++r) {
        // Issue next row's loads before consuming current row.
        float4 wn[IT];
        if (r + 1 < RPB) {
            const float4* __restrict__ wr =
                reinterpret_cast<const float4*>(W + (size_t)(row0 + r + 1) * KK);
#pragma unroll
            for (int t = 0; t < IT; ++t) wn[t] = wr[t * 256 + tid];
        }

        float a0 = 0.0f, a1 = 0.0f;
#pragma unroll
        for (int t = 0; t < IT; ++t) {
            a0 += wc[t].x * xa[t].x + wc[t].y * xa[t].y + wc[t].z * xa[t].z + wc[t].w * xa[t].w;
            a1 += wc[t].x * xb[t].x + wc[t].y * xb[t].y + wc[t].z * xb[t].z + wc[t].w * xb[t].w;
        }
#pragma unroll
        for (int off = 16; off; off >>= 1) {
            a0 += __shfl_xor_sync(0xFFFFFFFFu, a0, off);
            a1 += __shfl_xor_sync(0xFFFFFFFFu, a1, off);
        }
        if (lane == 0) { s0[r][warp] = a0; s1[r][warp] = a1; }

        if (r + 1 < RPB) {
#pragma unroll
            for (int t = 0; t < IT; ++t) wc[t] = wn[t];
        }
    }

    __syncthreads();
    // One thread per row finishes the reduction + epilogue.
    if (tid < RPB) {
        const int j = row0 + tid;
        float r0 = 0.0f, r1 = 0.0f;
#pragma unroll
        for (int w = 0; w < 8; ++w) { r0 += s0[tid][w]; r1 += s1[tid][w]; }
        float bb = b ? b[j] : 0.0f;
        r0 += bb; r1 += bb;
        if (RESID) { r0 += resid[j]; r1 += resid[N + j]; }
        if (RELU)  { r0 = fmaxf(r0, 0.0f); r1 = fmaxf(r1, 0.0f); }
        out[j]     = r0;
        out[N + j] = r1;
    }
}

// ---------------------------------------------------------------------------
// Stage 2: multi-head attention on the 2-token sequence (tiny; one block).
// ---------------------------------------------------------------------------
__global__ void k_attn() {
    __shared__ float s_scores[8];  // index: h*4 + l*2 + m
    __shared__ float s_attn[8];
    const int tid = threadIdx.x;          // 256 threads = 8 warps
    const int warp = tid >> 5, lane = tid & 31;

    // one warp per (h, l, m) combination
    const int h = warp >> 2, l = (warp >> 1) & 1, m = warp & 1;
    const float* __restrict__ q = g_qkv + l * 3 * D + h * HD;
    const float* __restrict__ k = g_qkv + m * 3 * D + D + h * HD;
    float acc = 0.0f;
#pragma unroll 4
    for (int i = lane; i < HD; i += 32) acc += q[i] * k[i];
#pragma unroll
    for (int off = 16; off; off >>= 1) acc += __shfl_xor_sync(0xFFFFFFFFu, acc, off);
    if (lane == 0) s_scores[warp] = acc * rsqrtf((float)HD);
    __syncthreads();

    if (tid < 4) {  // (h, l) pairs: softmax over m (2 elements)
        int hh = tid >> 1, ll = tid & 1;
        float s0v = s_scores[hh * 4 + ll * 2 + 0];
        float s1v = s_scores[hh * 4 + ll * 2 + 1];
        float mx = fmaxf(s0v, s1v);
        float e0 = __expf(s0v - mx), e1 = __expf(s1v - mx);
        float inv = 1.0f / (e0 + e1);
        s_attn[hh * 4 + ll * 2 + 0] = e0 * inv;
        s_attn[hh * 4 + ll * 2 + 1] = e1 * inv;
    }
    __syncthreads();

    for (int i = tid; i < 2 * D; i += blockDim.x) {
        int l2 = i / D;
        int d = i - l2 * D;
        int h2 = d / HD;
        float v0 = g_qkv[0 * 3 * D + 2 * D + d];
        float v1 = g_qkv[1 * 3 * D + 2 * D + d];
        g_o[i] = s_attn[h2 * 4 + l2 * 2 + 0] * v0 +
                 s_attn[h2 * 4 + l2 * 2 + 1] * v1;
    }
}

// ---------------------------------------------------------------------------
// Stage 7: out = 0.5 * dot(g0 + g1, exp_w2) + exp_b2
// ---------------------------------------------------------------------------
__global__ void k_final(const float* __restrict__ w2,
                        const float* __restrict__ b2,
                        float* __restrict__ out) {
    __shared__ float red[32];
    float acc = 0.0f;
    for (int i = threadIdx.x; i < E; i += blockDim.x)
        acc += (g_g[i] + g_g[E + i]) * w2[i];
#pragma unroll
    for (int off = 16; off; off >>= 1) acc += __shfl_xor_sync(0xFFFFFFFFu, acc, off);
    const int warp = threadIdx.x >> 5, lane = threadIdx.x & 31;
    if (lane == 0) red[warp] = acc;
    __syncthreads();
    if (threadIdx.x == 0) {
        float s = 0.0f;
        const int nw = blockDim.x >> 5;
        for (int w = 0; w < nw; ++w) s += red[w];
        out[0] = 0.5f * s + b2[0];
    }
}

// ---------------------------------------------------------------------------
extern "C" void kernel_launch(void* const* d_in, const int* in_sizes, int n_in,
                              void* d_out, int out_size) {
    const float* ray        = (const float*)d_in[0];
    const float* emb1_w     = (const float*)d_in[1];
    const float* emb1_b     = (const float*)d_in[2];
    const float* emb2_w     = (const float*)d_in[3];
    const float* emb2_b     = (const float*)d_in[4];
    const float* attn_in_w  = (const float*)d_in[5];
    const float* attn_in_b  = (const float*)d_in[6];
    const float* attn_out_w = (const float*)d_in[7];
    const float* attn_out_b = (const float*)d_in[8];
    const float* ffn1_w     = (const float*)d_in[9];
    const float* ffn1_b     = (const float*)d_in[10];
    const float* ffn2_w     = (const float*)d_in[11];
    const float* ffn2_b     = (const float*)d_in[12];
    const float* exp_w1     = (const float*)d_in[13];
    const float* exp_b1     = (const float*)d_in[14];
    const float* exp_w2     = (const float*)d_in[15];
    const float* exp_b2     = (const float*)d_in[16];
    // d_in[17] = idx (always 0, single expert) — unused
    float* out = (float*)d_out;

    float *px, *pqkv, *po, *px1, *ph, *px2, *pg;
    cudaGetSymbolAddress((void**)&px,   g_x);
    cudaGetSymbolAddress((void**)&pqkv, g_qkv);
    cudaGetSymbolAddress((void**)&po,   g_o);
    cudaGetSymbolAddress((void**)&px1,  g_x1);
    cudaGetSymbolAddress((void**)&ph,   g_h);
    cudaGetSymbolAddress((void**)&px2,  g_x2);
    cudaGetSymbolAddress((void**)&pg,   g_g);

    constexpr int RPB = 8;   // rows per block

    // 0: embeddings -> g_x [2][D]
    k_embed<<<(D + 255) / 256, 256>>>(ray, emb1_w, emb1_b, emb2_w, emb2_b);

    // 1: qkv = x @ attn_in_w^T + b  -> g_qkv [2][3D]   (201 MB of weights)
    k_gemv_pipe<D, false, false, RPB><<<(3 * D) / RPB, 256>>>(attn_in_w, attn_in_b, px, nullptr, pqkv, 3 * D);

    // 2: attention -> g_o [2][D]
    k_attn<<<1, 256>>>();

    // 3: x1 = x + o @ attn_out_w^T + b
    k_gemv_pipe<D, false, true, RPB><<<D / RPB, 256>>>(attn_out_w, attn_out_b, po, px, px1, D);

    // 4: h = relu(x1 @ ffn1_w^T + b1)
    k_gemv_pipe<D, true, false, RPB><<<D / RPB, 256>>>(ffn1_w, ffn1_b, px1, nullptr, ph, D);

    // 5: x2 = x1 + h @ ffn2_w^T + b2
    k_gemv_pipe<D, false, true, RPB><<<D / RPB, 256>>>(ffn2_w, ffn2_b, ph, px1, px2, D);

    // 6: g = relu(x2 @ exp_w1^T + b1)  -> [2][E]   (134 MB of weights)
    k_gemv_pipe<D, true, false, RPB><<<E / RPB, 256>>>(exp_w1, exp_b1, px2, nullptr, pg, E);

    // 7: out = mean over seq of (g @ exp_w2^T + b2)
    k_final<<<1, 1024>>>(exp_w2, exp_b2, out);
}